// round 10
// baseline (speedup 1.0000x reference)
#include <cuda_runtime.h>
#include <cuda_bf16.h>
#include <cuda_fp8.h>
#include <cstdint>

#define BS   4096
#define NROW 8192
#define D    512
#define EXP_SCALE 14.426950408889634f   // log2(e)/0.1
#define INV_T     10.0f

#define BM 128
#define BN 128
// K-chunk: 128 fp8 elements = 128 bytes/row; viewed as 64 "b16 units"
#define BKU 64            // b16 units per chunk
#define SSTRIDE 72        // b16 units: 64 data + 8 pad = 144 bytes/row
#define TILE_ELEMS (BM * SSTRIDE)          // b16 units per matrix per stage
#define SMEM_BYTES (4 * TILE_ELEMS * 2)    // 2 stages x (A+B) = 73728 B
#define NTILE (NROW / BM)                  // 64
#define NBLOCKS (NTILE * (NTILE + 1) / 2)  // 2080
#define NIT (D / 128)                      // 4 K-chunks

__device__ uint8_t g_reps[(size_t)NROW * D];   // e4m3, row-major 512 B/row
__device__ float g_rowsum[NROW];
__device__ float g_pos[NROW];

__device__ __forceinline__ float fast_ex2(float x) {
    float r; asm("ex2.approx.ftz.f32 %0, %1;" : "=f"(r) : "f"(x)); return r;
}
__device__ __forceinline__ void cp_async16(void* s, const void* g) {
    uint32_t saddr = (uint32_t)__cvta_generic_to_shared(s);
    asm volatile("cp.async.cg.shared.global [%0], [%1], 16;\n" :: "r"(saddr), "l"(g));
}
__device__ __forceinline__ void ldsm_x4(uint32_t& r0, uint32_t& r1,
                                        uint32_t& r2, uint32_t& r3, uint32_t addr) {
    asm volatile("ldmatrix.sync.aligned.m8n8.x4.shared.b16 {%0,%1,%2,%3}, [%4];"
                 : "=r"(r0), "=r"(r1), "=r"(r2), "=r"(r3) : "r"(addr));
}

// -------------------- normalize: fp32 -> e4m3 normalized rows --------------------
__global__ void normalize_kernel(const float* __restrict__ zi,
                                 const float* __restrict__ zj) {
    int row = blockIdx.x;
    const float* src = (row < BS) ? (zi + (size_t)row * D)
                                  : (zj + (size_t)(row - BS) * D);
    int t = threadIdx.x;  // 128 threads x 4 floats
    float4 v = ((const float4*)src)[t];
    float ss = v.x * v.x + v.y * v.y + v.z * v.z + v.w * v.w;
    #pragma unroll
    for (int o = 16; o; o >>= 1) ss += __shfl_xor_sync(~0u, ss, o);
    __shared__ float wss[4];
    if ((t & 31) == 0) wss[t >> 5] = ss;
    __syncthreads();
    float inv = rsqrtf(wss[0] + wss[1] + wss[2] + wss[3]);
    __nv_fp8x2_storage_t lo = __nv_cvt_float2_to_fp8x2(
        make_float2(v.x * inv, v.y * inv), __NV_SATFINITE, __NV_E4M3);
    __nv_fp8x2_storage_t hi = __nv_cvt_float2_to_fp8x2(
        make_float2(v.z * inv, v.w * inv), __NV_SATFINITE, __NV_E4M3);
    uint32_t packed = (uint32_t)lo | ((uint32_t)hi << 16);
    ((uint32_t*)(g_reps + (size_t)row * D))[t] = packed;
    if (t == 0) { g_rowsum[row] = 0.0f; g_pos[row] = 0.0f; }
}

// ------- sim kernel: 8 warps 32x64, FP8 m16n8k32 HMMA + ldmatrix -------
__global__ void __launch_bounds__(256, 2) sim_kernel() {
    // triangular decode: linear id -> (bi, bj), bj >= bi
    int idx = blockIdx.x;
    float fi = (2.0f * NTILE + 1.0f
                - sqrtf((2.0f * NTILE + 1.0f) * (2.0f * NTILE + 1.0f)
                        - 8.0f * (float)idx)) * 0.5f;
    int bi = (int)fi;
    while (bi * NTILE - (bi * (bi - 1)) / 2 > idx) bi--;
    while ((bi + 1) * NTILE - ((bi + 1) * bi) / 2 <= idx) bi++;
    int bj = bi + (idx - (bi * NTILE - (bi * (bi - 1)) / 2));

    extern __shared__ __nv_bfloat16 sm[];   // raw storage, b16-unit addressed
    __nv_bfloat16* bufA[2] = { sm,              sm + 2 * TILE_ELEMS };
    __nv_bfloat16* bufB[2] = { sm + TILE_ELEMS, sm + 3 * TILE_ELEMS };

    const int t = threadIdx.x;
    const int warp = t >> 5, lane = t & 31;
    const int wm = warp >> 1, wn = warp & 1;   // 4x2 warps, warp tile 32x64
    const int lr = t >> 3;   // 0..31 (cp.async row)
    const int lc = t & 7;    // 0..7  (16B chunk in 128B row)

    // ldmatrix lane offsets in b16 units (byte layout of fp8 k32 frag ==
    // bf16 k16 frag), x2 for bytes applied at use
    const int row_in = lane & 7, grp = lane >> 3;
    int offA[2];
    #pragma unroll
    for (int mi = 0; mi < 2; mi++)
        offA[mi] = (wm * 32 + mi * 16 + (grp & 1) * 8 + row_in) * SSTRIDE
                 + (grp >> 1) * 8;
    int offB[4];
    #pragma unroll
    for (int p = 0; p < 4; p++)
        offB[p] = (wn * 64 + (2 * p + (grp >> 1)) * 8 + row_in) * SSTRIDE
                + (grp & 1) * 8;

    float acc[2][8][4];
    #pragma unroll
    for (int mi = 0; mi < 2; mi++)
        #pragma unroll
        for (int ni = 0; ni < 8; ni++)
            #pragma unroll
            for (int c = 0; c < 4; c++) acc[mi][ni][c] = 0.0f;

    const size_t arow = (size_t)(bi * BM) * D;   // bytes
    const size_t brow = (size_t)(bj * BN) * D;

    // prefetch chunk 0: each row 128 bytes = 8 x 16B
    #pragma unroll
    for (int p = 0; p < 4; p++) {
        int r = lr + 32 * p;
        cp_async16((char*)bufA[0] + r * 144 + lc * 16,
                   g_reps + arow + (size_t)r * D + lc * 16);
        cp_async16((char*)bufB[0] + r * 144 + lc * 16,
                   g_reps + brow + (size_t)r * D + lc * 16);
    }
    asm volatile("cp.async.commit_group;\n");

    for (int it = 0; it < NIT; it++) {
        if (it + 1 < NIT) {
            int nb = (it + 1) & 1, kk = (it + 1) * 128;
            #pragma unroll
            for (int p = 0; p < 4; p++) {
                int r = lr + 32 * p;
                cp_async16((char*)bufA[nb] + r * 144 + lc * 16,
                           g_reps + arow + (size_t)r * D + kk + lc * 16);
                cp_async16((char*)bufB[nb] + r * 144 + lc * 16,
                           g_reps + brow + (size_t)r * D + kk + lc * 16);
            }
            asm volatile("cp.async.commit_group;\n");
            asm volatile("cp.async.wait_group 1;\n");
        } else {
            asm volatile("cp.async.wait_group 0;\n");
        }
        __syncthreads();

        const uint32_t sA = (uint32_t)__cvta_generic_to_shared(bufA[it & 1]);
        const uint32_t sB = (uint32_t)__cvta_generic_to_shared(bufB[it & 1]);

        // 4 k32 steps per chunk; step stride = 16 b16 units = 32 fp8
        #pragma unroll
        for (int k16 = 0; k16 < BKU; k16 += 16) {
            uint32_t a[2][4], b[8][2];
            #pragma unroll
            for (int mi = 0; mi < 2; mi++)
                ldsm_x4(a[mi][0], a[mi][1], a[mi][2], a[mi][3],
                        sA + (uint32_t)(offA[mi] + k16) * 2u);
            #pragma unroll
            for (int p = 0; p < 4; p++)
                ldsm_x4(b[2 * p][0], b[2 * p][1], b[2 * p + 1][0], b[2 * p + 1][1],
                        sB + (uint32_t)(offB[p] + k16) * 2u);
            #pragma unroll
            for (int mi = 0; mi < 2; mi++)
                #pragma unroll
                for (int ni = 0; ni < 8; ni++) {
                    asm volatile(
                        "mma.sync.aligned.m16n8k32.row.col.f32.e4m3.e4m3.f32 "
                        "{%0,%1,%2,%3}, {%4,%5,%6,%7}, {%8,%9}, {%0,%1,%2,%3};\n"
                        : "+f"(acc[mi][ni][0]), "+f"(acc[mi][ni][1]),
                          "+f"(acc[mi][ni][2]), "+f"(acc[mi][ni][3])
                        : "r"(a[mi][0]), "r"(a[mi][1]), "r"(a[mi][2]), "r"(a[mi][3]),
                          "r"(b[ni][0]), "r"(b[ni][1]));
                }
        }
        __syncthreads();
    }

    // ---- Epilogue (same accumulator layout as bf16 m16n8k16) ----
    const int gi_base = bi * BM + wm * 32 + (lane >> 2);
    const int gj_base = bj * BN + wn * 64 + (lane & 3) * 2;

    if (bi == bj) {
        float rp[4] = {0.f, 0.f, 0.f, 0.f};
        #pragma unroll
        for (int mi = 0; mi < 2; mi++)
            #pragma unroll
            for (int ni = 0; ni < 8; ni++)
                #pragma unroll
                for (int c = 0; c < 4; c++) {
                    int gi = gi_base + mi * 16 + (c >> 1) * 8;
                    int gj = gj_base + ni * 8 + (c & 1);
                    float e = fast_ex2(acc[mi][ni][c] * EXP_SCALE);
                    if (gi != gj) rp[mi * 2 + (c >> 1)] += e;
                }
        #pragma unroll
        for (int r4 = 0; r4 < 4; r4++) {
            rp[r4] += __shfl_xor_sync(~0u, rp[r4], 1);
            rp[r4] += __shfl_xor_sync(~0u, rp[r4], 2);
        }
        if ((lane & 3) == 0) {
            atomicAdd(&g_rowsum[gi_base     ], rp[0]);
            atomicAdd(&g_rowsum[gi_base +  8], rp[1]);
            atomicAdd(&g_rowsum[gi_base + 16], rp[2]);
            atomicAdd(&g_rowsum[gi_base + 24], rp[3]);
        }
    } else {
        float rp[4] = {0.f, 0.f, 0.f, 0.f};
        float cs[8][2];
        #pragma unroll
        for (int ni = 0; ni < 8; ni++) { cs[ni][0] = 0.f; cs[ni][1] = 0.f; }
        const bool pos_tile = (bj == bi + BS / BM);
        #pragma unroll
        for (int mi = 0; mi < 2; mi++)
            #pragma unroll
            for (int ni = 0; ni < 8; ni++)
                #pragma unroll
                for (int c = 0; c < 4; c++) {
                    int gi = gi_base + mi * 16 + (c >> 1) * 8;
                    int gj = gj_base + ni * 8 + (c & 1);
                    float val = acc[mi][ni][c];
                    float e = fast_ex2(val * EXP_SCALE);
                    rp[mi * 2 + (c >> 1)] += e;
                    cs[ni][c & 1] += e;
                    if (pos_tile && gj == gi + BS) {
                        g_pos[gi] = val;
                        g_pos[gj] = val;
                    }
                }
        #pragma unroll
        for (int r4 = 0; r4 < 4; r4++) {
            rp[r4] += __shfl_xor_sync(~0u, rp[r4], 1);
            rp[r4] += __shfl_xor_sync(~0u, rp[r4], 2);
        }
        if ((lane & 3) == 0) {
            atomicAdd(&g_rowsum[gi_base     ], rp[0]);
            atomicAdd(&g_rowsum[gi_base +  8], rp[1]);
            atomicAdd(&g_rowsum[gi_base + 16], rp[2]);
            atomicAdd(&g_rowsum[gi_base + 24], rp[3]);
        }
        #pragma unroll
        for (int ni = 0; ni < 8; ni++) {
            #pragma unroll
            for (int p = 0; p < 2; p++) {
                cs[ni][p] += __shfl_xor_sync(~0u, cs[ni][p], 4);
                cs[ni][p] += __shfl_xor_sync(~0u, cs[ni][p], 8);
                cs[ni][p] += __shfl_xor_sync(~0u, cs[ni][p], 16);
            }
        }
        if ((lane >> 2) == 0) {
            #pragma unroll
            for (int ni = 0; ni < 8; ni++) {
                int gj = bj * BN + wn * 64 + ni * 8 + (lane & 3) * 2;
                atomicAdd(&g_rowsum[gj    ], cs[ni][0]);
                atomicAdd(&g_rowsum[gj + 1], cs[ni][1]);
            }
        }
    }
}

// -------------------- loss --------------------
__global__ void loss_kernel(float* __restrict__ out) {
    int t = threadIdx.x;  // 1024
    float s = 0.0f;
    for (int i = t; i < NROW; i += 1024)
        s += logf(g_rowsum[i]) - g_pos[i] * INV_T;
    #pragma unroll
    for (int o = 16; o; o >>= 1) s += __shfl_xor_sync(~0u, s, o);
    __shared__ float wsum[32];
    if ((t & 31) == 0) wsum[t >> 5] = s;
    __syncthreads();
    if (t == 0) {
        float tot = 0.0f;
        #pragma unroll
        for (int w = 0; w < 32; w++) tot += wsum[w];
        out[0] = tot / (float)NROW;
    }
}

extern "C" void kernel_launch(void* const* d_in, const int* in_sizes, int n_in,
                              void* d_out, int out_size) {
    const float* zi = (const float*)d_in[0];
    const float* zj = (const float*)d_in[1];
    cudaFuncSetAttribute(sim_kernel, cudaFuncAttributeMaxDynamicSharedMemorySize,
                         SMEM_BYTES);
    normalize_kernel<<<NROW, 128>>>(zi, zj);
    sim_kernel<<<NBLOCKS, 256, SMEM_BYTES>>>();
    loss_kernel<<<1, 1024>>>((float*)d_out);
}

// round 11
// speedup vs baseline: 1.1030x; 1.1030x over previous
#include <cuda_runtime.h>
#include <cuda_bf16.h>
#include <cstdint>

#define BS   4096
#define NROW 8192
#define D    512
#define EXP_SCALE 14.426950408889634f   // log2(e)/0.1
#define INV_T     10.0f

#define BM 128
#define BN 128
#define BK 64
#define SSTRIDE 72        // 64 data bf16 + 8 pad
#define TILE_ELEMS (BM * SSTRIDE)
#define SMEM_BYTES (4 * TILE_ELEMS * 2)   // 2 buffers x (A+B) x bf16 = 73728 B
#define NTILE (NROW / BM)                  // 64
#define NBLOCKS (NTILE * (NTILE + 1) / 2)  // 2080

__device__ __nv_bfloat16 g_reps[(size_t)NROW * D];
__device__ float g_rowsum[NROW];
__device__ float g_pos[NROW];

__device__ __forceinline__ float fast_ex2(float x) {
    float r; asm("ex2.approx.ftz.f32 %0, %1;" : "=f"(r) : "f"(x)); return r;
}
__device__ __forceinline__ void cp_async16(void* s, const void* g) {
    uint32_t saddr = (uint32_t)__cvta_generic_to_shared(s);
    asm volatile("cp.async.cg.shared.global [%0], [%1], 16;\n" :: "r"(saddr), "l"(g));
}
__device__ __forceinline__ void ldsm_x4(uint32_t& r0, uint32_t& r1,
                                        uint32_t& r2, uint32_t& r3, uint32_t addr) {
    asm volatile("ldmatrix.sync.aligned.m8n8.x4.shared.b16 {%0,%1,%2,%3}, [%4];"
                 : "=r"(r0), "=r"(r1), "=r"(r2), "=r"(r3) : "r"(addr));
}

// ---------- normalize: warp-per-row, no smem, no block barrier ----------
__global__ void __launch_bounds__(256) normalize_kernel(const float* __restrict__ zi,
                                                        const float* __restrict__ zj) {
    const int warp = threadIdx.x >> 5, lane = threadIdx.x & 31;
    const int row = blockIdx.x * 8 + warp;
    const float* src = (row < BS) ? (zi + (size_t)row * D)
                                  : (zj + (size_t)(row - BS) * D);
    const float4* src4 = (const float4*)src;   // 128 float4 per row
    float4 v[4];
    float ss = 0.0f;
    #pragma unroll
    for (int i = 0; i < 4; i++) {
        v[i] = src4[lane + 32 * i];
        ss += v[i].x * v[i].x + v[i].y * v[i].y + v[i].z * v[i].z + v[i].w * v[i].w;
    }
    #pragma unroll
    for (int o = 16; o; o >>= 1) ss += __shfl_xor_sync(~0u, ss, o);
    float inv = rsqrtf(ss);
    uint2* dst = (uint2*)(g_reps + (size_t)row * D);   // 8B per float4 chunk
    #pragma unroll
    for (int i = 0; i < 4; i++) {
        __nv_bfloat162 lo = __floats2bfloat162_rn(v[i].x * inv, v[i].y * inv);
        __nv_bfloat162 hi = __floats2bfloat162_rn(v[i].z * inv, v[i].w * inv);
        uint2 pk;
        pk.x = *(uint32_t*)&lo;
        pk.y = *(uint32_t*)&hi;
        dst[lane + 32 * i] = pk;
    }
    if (lane == 0) { g_rowsum[row] = 0.0f; g_pos[row] = 0.0f; }
}

// -------- sim kernel (R6 best config): 8 warps 32x64, HMMA + ldmatrix --------
__global__ void __launch_bounds__(256, 2) sim_kernel() {
    // triangular decode: linear id -> (bi, bj), bj >= bi
    int idx = blockIdx.x;
    float fi = (2.0f * NTILE + 1.0f
                - sqrtf((2.0f * NTILE + 1.0f) * (2.0f * NTILE + 1.0f)
                        - 8.0f * (float)idx)) * 0.5f;
    int bi = (int)fi;
    while (bi * NTILE - (bi * (bi - 1)) / 2 > idx) bi--;
    while ((bi + 1) * NTILE - ((bi + 1) * bi) / 2 <= idx) bi++;
    int bj = bi + (idx - (bi * NTILE - (bi * (bi - 1)) / 2));

    extern __shared__ __nv_bfloat16 sm[];
    __nv_bfloat16* bufA[2] = { sm,              sm + 2 * TILE_ELEMS };
    __nv_bfloat16* bufB[2] = { sm + TILE_ELEMS, sm + 3 * TILE_ELEMS };

    const int t = threadIdx.x;
    const int warp = t >> 5, lane = t & 31;
    const int wm = warp >> 1, wn = warp & 1;
    const int lr = t >> 3;   // 0..31 (cp.async row)
    const int lc = t & 7;    // 0..7  (16B chunk)

    const int row_in = lane & 7, grp = lane >> 3;
    int offA[2];
    #pragma unroll
    for (int mi = 0; mi < 2; mi++)
        offA[mi] = (wm * 32 + mi * 16 + (grp & 1) * 8 + row_in) * SSTRIDE
                 + (grp >> 1) * 8;
    int offB[4];
    #pragma unroll
    for (int p = 0; p < 4; p++)
        offB[p] = (wn * 64 + (2 * p + (grp >> 1)) * 8 + row_in) * SSTRIDE
                + (grp & 1) * 8;

    float acc[2][8][4];
    #pragma unroll
    for (int mi = 0; mi < 2; mi++)
        #pragma unroll
        for (int ni = 0; ni < 8; ni++)
            #pragma unroll
            for (int c = 0; c < 4; c++) acc[mi][ni][c] = 0.0f;

    // prefetch tile 0
    #pragma unroll
    for (int p = 0; p < 4; p++) {
        int r = lr + 32 * p;
        cp_async16(bufA[0] + r * SSTRIDE + lc * 8,
                   g_reps + (size_t)(bi * BM + r) * D + lc * 8);
        cp_async16(bufB[0] + r * SSTRIDE + lc * 8,
                   g_reps + (size_t)(bj * BN + r) * D + lc * 8);
    }
    asm volatile("cp.async.commit_group;\n");

    const int NIT = D / BK;   // 8
    for (int it = 0; it < NIT; it++) {
        if (it + 1 < NIT) {
            int nb = (it + 1) & 1, kk = (it + 1) * BK;
            #pragma unroll
            for (int p = 0; p < 4; p++) {
                int r = lr + 32 * p;
                cp_async16(bufA[nb] + r * SSTRIDE + lc * 8,
                           g_reps + (size_t)(bi * BM + r) * D + kk + lc * 8);
                cp_async16(bufB[nb] + r * SSTRIDE + lc * 8,
                           g_reps + (size_t)(bj * BN + r) * D + kk + lc * 8);
            }
            asm volatile("cp.async.commit_group;\n");
            asm volatile("cp.async.wait_group 1;\n");
        } else {
            asm volatile("cp.async.wait_group 0;\n");
        }
        __syncthreads();

        const uint32_t sA = (uint32_t)__cvta_generic_to_shared(bufA[it & 1]);
        const uint32_t sB = (uint32_t)__cvta_generic_to_shared(bufB[it & 1]);

        #pragma unroll
        for (int k16 = 0; k16 < BK; k16 += 16) {
            uint32_t a[2][4], b[8][2];
            #pragma unroll
            for (int mi = 0; mi < 2; mi++)
                ldsm_x4(a[mi][0], a[mi][1], a[mi][2], a[mi][3],
                        sA + (uint32_t)(offA[mi] + k16) * 2u);
            #pragma unroll
            for (int p = 0; p < 4; p++)
                ldsm_x4(b[2 * p][0], b[2 * p][1], b[2 * p + 1][0], b[2 * p + 1][1],
                        sB + (uint32_t)(offB[p] + k16) * 2u);
            #pragma unroll
            for (int mi = 0; mi < 2; mi++)
                #pragma unroll
                for (int ni = 0; ni < 8; ni++) {
                    asm volatile(
                        "mma.sync.aligned.m16n8k16.row.col.f32.bf16.bf16.f32 "
                        "{%0,%1,%2,%3}, {%4,%5,%6,%7}, {%8,%9}, {%0,%1,%2,%3};\n"
                        : "+f"(acc[mi][ni][0]), "+f"(acc[mi][ni][1]),
                          "+f"(acc[mi][ni][2]), "+f"(acc[mi][ni][3])
                        : "r"(a[mi][0]), "r"(a[mi][1]), "r"(a[mi][2]), "r"(a[mi][3]),
                          "r"(b[ni][0]), "r"(b[ni][1]));
                }
        }
        __syncthreads();
    }

    // ---- Epilogue ----
    const int gi_base = bi * BM + wm * 32 + (lane >> 2);
    const int gj_base = bj * BN + wn * 64 + (lane & 3) * 2;

    if (bi == bj) {
        float rp[4] = {0.f, 0.f, 0.f, 0.f};
        #pragma unroll
        for (int mi = 0; mi < 2; mi++)
            #pragma unroll
            for (int ni = 0; ni < 8; ni++)
                #pragma unroll
                for (int c = 0; c < 4; c++) {
                    int gi = gi_base + mi * 16 + (c >> 1) * 8;
                    int gj = gj_base + ni * 8 + (c & 1);
                    float e = fast_ex2(acc[mi][ni][c] * EXP_SCALE);
                    if (gi != gj) rp[mi * 2 + (c >> 1)] += e;
                }
        #pragma unroll
        for (int r4 = 0; r4 < 4; r4++) {
            rp[r4] += __shfl_xor_sync(~0u, rp[r4], 1);
            rp[r4] += __shfl_xor_sync(~0u, rp[r4], 2);
        }
        if ((lane & 3) == 0) {
            atomicAdd(&g_rowsum[gi_base     ], rp[0]);
            atomicAdd(&g_rowsum[gi_base +  8], rp[1]);
            atomicAdd(&g_rowsum[gi_base + 16], rp[2]);
            atomicAdd(&g_rowsum[gi_base + 24], rp[3]);
        }
    } else {
        float rp[4] = {0.f, 0.f, 0.f, 0.f};
        float cs[8][2];
        #pragma unroll
        for (int ni = 0; ni < 8; ni++) { cs[ni][0] = 0.f; cs[ni][1] = 0.f; }
        const bool pos_tile = (bj == bi + BS / BM);
        #pragma unroll
        for (int mi = 0; mi < 2; mi++)
            #pragma unroll
            for (int ni = 0; ni < 8; ni++)
                #pragma unroll
                for (int c = 0; c < 4; c++) {
                    int gi = gi_base + mi * 16 + (c >> 1) * 8;
                    int gj = gj_base + ni * 8 + (c & 1);
                    float val = acc[mi][ni][c];
                    float e = fast_ex2(val * EXP_SCALE);
                    rp[mi * 2 + (c >> 1)] += e;
                    cs[ni][c & 1] += e;
                    if (pos_tile && gj == gi + BS) {
                        g_pos[gi] = val;
                        g_pos[gj] = val;
                    }
                }
        #pragma unroll
        for (int r4 = 0; r4 < 4; r4++) {
            rp[r4] += __shfl_xor_sync(~0u, rp[r4], 1);
            rp[r4] += __shfl_xor_sync(~0u, rp[r4], 2);
        }
        if ((lane & 3) == 0) {
            atomicAdd(&g_rowsum[gi_base     ], rp[0]);
            atomicAdd(&g_rowsum[gi_base +  8], rp[1]);
            atomicAdd(&g_rowsum[gi_base + 16], rp[2]);
            atomicAdd(&g_rowsum[gi_base + 24], rp[3]);
        }
        #pragma unroll
        for (int ni = 0; ni < 8; ni++) {
            #pragma unroll
            for (int p = 0; p < 2; p++) {
                cs[ni][p] += __shfl_xor_sync(~0u, cs[ni][p], 4);
                cs[ni][p] += __shfl_xor_sync(~0u, cs[ni][p], 8);
                cs[ni][p] += __shfl_xor_sync(~0u, cs[ni][p], 16);
            }
        }
        if ((lane >> 2) == 0) {
            #pragma unroll
            for (int ni = 0; ni < 8; ni++) {
                int gj = bj * BN + wn * 64 + ni * 8 + (lane & 3) * 2;
                atomicAdd(&g_rowsum[gj    ], cs[ni][0]);
                atomicAdd(&g_rowsum[gj + 1], cs[ni][1]);
            }
        }
    }
}

// -------------------- loss --------------------
__global__ void loss_kernel(float* __restrict__ out) {
    int t = threadIdx.x;  // 1024
    float s0 = 0.f, s1 = 0.f, s2 = 0.f, s3 = 0.f;
    #pragma unroll
    for (int i = 0; i < 8; i += 4) {
        s0 += logf(g_rowsum[t + (i    ) * 1024]) - g_pos[t + (i    ) * 1024] * INV_T;
        s1 += logf(g_rowsum[t + (i + 1) * 1024]) - g_pos[t + (i + 1) * 1024] * INV_T;
        s2 += logf(g_rowsum[t + (i + 2) * 1024]) - g_pos[t + (i + 2) * 1024] * INV_T;
        s3 += logf(g_rowsum[t + (i + 3) * 1024]) - g_pos[t + (i + 3) * 1024] * INV_T;
    }
    float s = (s0 + s1) + (s2 + s3);
    #pragma unroll
    for (int o = 16; o; o >>= 1) s += __shfl_xor_sync(~0u, s, o);
    __shared__ float wsum[32];
    if ((t & 31) == 0) wsum[t >> 5] = s;
    __syncthreads();
    if (t == 0) {
        float tot = 0.0f;
        #pragma unroll
        for (int w = 0; w < 32; w++) tot += wsum[w];
        out[0] = tot / (float)NROW;
    }
}

extern "C" void kernel_launch(void* const* d_in, const int* in_sizes, int n_in,
                              void* d_out, int out_size) {
    const float* zi = (const float*)d_in[0];
    const float* zj = (const float*)d_in[1];
    cudaFuncSetAttribute(sim_kernel, cudaFuncAttributeMaxDynamicSharedMemorySize,
                         SMEM_BYTES);
    normalize_kernel<<<NROW / 8, 256>>>(zi, zj);
    sim_kernel<<<NBLOCKS, 256, SMEM_BYTES>>>();
    loss_kernel<<<1, 1024>>>((float*)d_out);
}